// round 6
// baseline (speedup 1.0000x reference)
#include <cuda_runtime.h>
#include <math.h>
#include <stdint.h>

// Problem geometry (fixed by the dataset)
#define N0c 1048576
#define N1c 65536
#define N2c 4096
#define DEG0c 16
#define DEG1c 10
#define DINc 128
#define DHc 256
#define DOUTc 47
#define E1c (N2c * DEG1c)

// Scratch (alloc-free: __device__ globals)
__device__ float g_agg0[(size_t)N1c * DINc];   // 32 MB (compact rows)
__device__ float g_h0  [(size_t)N1c * DHc];    // 64 MB (compact rows)
__device__ float g_agg1[(size_t)N2c * DHc];    //  4 MB
__device__ int   g_mask [N1c];
__device__ int   g_list [N1c];                 // compact row -> node id
__device__ int   g_remap[N1c];                 // node id -> compact row
__device__ int   g_cnt;

__device__ __forceinline__ float gelu_exact(float v) {
    return 0.5f * v * (1.0f + erff(v * 0.7071067811865476f));
}

__device__ __forceinline__ uint32_t f2tf32(float f) {
    uint32_t u;
    asm("cvt.rna.tf32.f32 %0, %1;" : "=r"(u) : "f"(f));
    return u;
}
__device__ __forceinline__ uint32_t tf32r(uint32_t raw) {   // fp32 bits -> tf32 bits
    uint32_t u;
    asm("cvt.rna.tf32.f32 %0, %1;" : "=r"(u) : "f"(__uint_as_float(raw)));
    return u;
}

__device__ __forceinline__ void cp16(uint32_t saddr, const void* gaddr) {
    asm volatile("cp.async.cg.shared.global [%0], [%1], 16;\n" :: "r"(saddr), "l"(gaddr));
}

// ---------------------------------------------------------------------------
// Dedup pipeline
// ---------------------------------------------------------------------------
__global__ void init_kernel(int* mask, int* list, int* cnt)
{
    int t = blockIdx.x * blockDim.x + threadIdx.x;
    mask[t] = (t < N2c) ? 1 : 0;   // seeds always needed
    list[t] = 0;                    // padding rows alias node 0
    if (t == 0) *cnt = 0;
}

__global__ void mark_kernel(const int* __restrict__ idx1, int* mask)
{
    int t = blockIdx.x * blockDim.x + threadIdx.x;
    if (t < E1c) mask[idx1[t]] = 1;
}

__global__ void compact_kernel(const int* __restrict__ mask, int* list,
                               int* remap, int* cnt)
{
    const int n = blockIdx.x * blockDim.x + threadIdx.x;
    const int lane = threadIdx.x & 31;
    const int m = (n < N1c) ? mask[n] : 0;
    const unsigned bal = __ballot_sync(0xffffffffu, m);
    const int total = __popc(bal);
    int base = 0;
    if (lane == 0 && total) base = atomicAdd(cnt, total);
    base = __shfl_sync(0xffffffffu, base, 0);
    if (m) {
        const int p = base + __popc(bal & ((1u << lane) - 1u));
        list[p] = n;
        remap[n] = p;
    }
}

// ---------------------------------------------------------------------------
// Mean aggregation, cp.async-staged
// ---------------------------------------------------------------------------
template<int D, int DEG, int NDST, bool DLIST, bool SRCMAP>
__global__ void __launch_bounds__(256)
agg_cp_kernel(const float* __restrict__ x, const int* __restrict__ idx,
              float* __restrict__ out,
              const int* __restrict__ dlist, const int* __restrict__ srcmap,
              const int* __restrict__ cntp)
{
    constexpr int C4   = D / 4;
    constexpr int NCHK = NDST * DEG * C4;
    constexpr int PER  = NCHK / 256;

    const int dst0 = blockIdx.x * NDST;
    if (DLIST) {
        const int cnt_pad = (*cntp + 127) & ~127;
        if (dst0 >= cnt_pad) return;
    }

    extern __shared__ float4 sbuf[];
    const uint32_t sbase = (uint32_t)__cvta_generic_to_shared(sbuf);
    const int tid = threadIdx.x;

    #pragma unroll
    for (int p = 0; p < PER; p++) {
        const int c   = tid + p * 256;
        const int eg  = c / C4;
        const int col = c % C4;
        const int dl  = eg / DEG;
        const int e   = eg % DEG;
        const int node = DLIST ? dlist[dst0 + dl] : (dst0 + dl);
        int src = idx[(size_t)node * DEG + e];
        if (SRCMAP) src = srcmap[src];
        cp16(sbase + (uint32_t)c * 16u, x + (size_t)src * D + col * 4);
    }
    asm volatile("cp.async.commit_group;\n" ::);
    asm volatile("cp.async.wait_group 0;\n" ::);
    __syncthreads();

    constexpr int WPD = 8 / NDST;
    const int warp = tid >> 5, lane = tid & 31;
    const int dl   = warp / WPD;
    const int half = warp % WPD;
    const int col  = half * 32 + lane;

    float4 acc = make_float4(0.f, 0.f, 0.f, 0.f);
    #pragma unroll
    for (int e = 0; e < DEG; e++) {
        float4 v = sbuf[(dl * DEG + e) * C4 + col];
        acc.x += v.x; acc.y += v.y; acc.z += v.z; acc.w += v.w;
    }
    const float inv = 1.0f / (float)DEG;
    ((float4*)(out + (size_t)(dst0 + dl) * D))[col] =
        make_float4(acc.x * inv, acc.y * inv, acc.z * inv, acc.w * inv);
}

// ---------------------------------------------------------------------------
// tf32 GEMM, BM=64, BN=256 (full output width), BK=32, cp.async double-buffer.
//   C[M,256] = gelu([A1|A2g] @ [W1|W2]^T + bias)
// 8 warps, warp tile 32x64 (acc[2][8][4]). tf32 cvt applied on fragments.
// FUSE_PROJ: instead of storing C, run second GEMM vs Wo (47x256) entirely
// in smem and store out[M,47] = h1 @ Wo^T + bo.
// ---------------------------------------------------------------------------
template<bool FUSE_PROJ>
__global__ void __launch_bounds__(256)
gemm_n256(const float* __restrict__ A1, const float* __restrict__ A2,
          int K1, int K2,
          const float* __restrict__ W1, const float* __restrict__ W2,
          const float* __restrict__ bias,
          float* __restrict__ C,
          const int* __restrict__ rowA2, const int* __restrict__ cntp,
          const float* __restrict__ Wo, const float* __restrict__ bo)
{
    constexpr int SA = 36;
    constexpr int AW = 64 * SA;        // words per A buffer   (2304)
    constexpr int WW = 256 * SA;       // words per W buffer   (9216)

    const int m0 = blockIdx.x * 64;
    if (cntp) {
        const int mpad = (*cntp + 63) & ~63;
        if (m0 >= mpad) return;
    }

    extern __shared__ uint32_t sm[];
    uint32_t* As = sm;                 // [2][AW]
    uint32_t* Ws = sm + 2 * AW;        // [2][WW]  (aliased by h1 tile in proj)

    const int tid  = threadIdx.x;
    const int lane = tid & 31;
    const int warp = tid >> 5;
    const int warpM = warp & 1;        // 2 x 32 rows
    const int warpN = warp >> 1;       // 4 x 64 cols
    const int lrow8 = tid >> 3;        // 0..31
    const int lcol  = (tid & 7) * 4;   // 0..28

    const uint32_t sA = (uint32_t)__cvta_generic_to_shared(As);
    const uint32_t sW = (uint32_t)__cvta_generic_to_shared(Ws);

    auto fetch = [&](int it, int buf) {
        const int gk = it * 32 + lcol;
        #pragma unroll
        for (int p = 0; p < 2; p++) {
            const int r = lrow8 + p * 32;
            const int m = m0 + r;
            const float* src;
            if (gk < K1) {
                src = A1 + (size_t)m * K1 + gk;
            } else {
                const int mr = rowA2 ? rowA2[m] : m;
                src = A2 + (size_t)mr * K2 + (gk - K1);
            }
            cp16(sA + (uint32_t)(buf * AW + r * SA + lcol) * 4u, src);
        }
        #pragma unroll
        for (int p = 0; p < 8; p++) {
            const int nr = lrow8 + p * 32;
            const float* src = (gk < K1)
                ? W1 + (size_t)nr * K1 + gk
                : W2 + (size_t)nr * K2 + (gk - K1);
            cp16(sW + (uint32_t)(buf * WW + nr * SA + lcol) * 4u, src);
        }
    };

    float acc[2][8][4] = {};

    const int quad = lane >> 3, qr = lane & 7;
    const int aRowB = warpM * 32 + (quad & 1) * 8 + qr;
    const int aColB = (quad >> 1) * 4;
    const int bq = (lane & 15) >> 3, br = lane & 7;
    const int bRowB = warpN * 64 + br;
    const int bColB = bq * 4;

    fetch(0, 0);
    asm volatile("cp.async.commit_group;\n" ::);

    const int nk = (K1 + K2) / 32;
    int buf = 0;
    for (int it = 0; it < nk; it++) {
        if (it + 1 < nk) {
            fetch(it + 1, buf ^ 1);
            asm volatile("cp.async.commit_group;\n" ::);
            asm volatile("cp.async.wait_group 1;\n" ::);
        } else {
            asm volatile("cp.async.wait_group 0;\n" ::);
        }
        __syncthreads();

        const uint32_t baseA = sA + (uint32_t)(buf * AW) * 4u;
        const uint32_t baseW = sW + (uint32_t)(buf * WW) * 4u;

        #pragma unroll
        for (int ks = 0; ks < 4; ks++) {
            uint32_t a[2][4], b[8][2];
            #pragma unroll
            for (int mi = 0; mi < 2; mi++) {
                uint32_t ad = baseA + (uint32_t)(((aRowB + mi * 16) * SA) + ks * 8 + aColB) * 4u;
                asm volatile("ldmatrix.sync.aligned.m8n8.x4.shared.b16 {%0,%1,%2,%3}, [%4];\n"
                             : "=r"(a[mi][0]), "=r"(a[mi][1]), "=r"(a[mi][2]), "=r"(a[mi][3])
                             : "r"(ad));
                a[mi][0] = tf32r(a[mi][0]); a[mi][1] = tf32r(a[mi][1]);
                a[mi][2] = tf32r(a[mi][2]); a[mi][3] = tf32r(a[mi][3]);
            }
            #pragma unroll
            for (int ni = 0; ni < 8; ni++) {
                uint32_t bd = baseW + (uint32_t)(((bRowB + ni * 8) * SA) + ks * 8 + bColB) * 4u;
                asm volatile("ldmatrix.sync.aligned.m8n8.x2.shared.b16 {%0,%1}, [%2];\n"
                             : "=r"(b[ni][0]), "=r"(b[ni][1])
                             : "r"(bd));
                b[ni][0] = tf32r(b[ni][0]); b[ni][1] = tf32r(b[ni][1]);
            }
            #pragma unroll
            for (int mi = 0; mi < 2; mi++)
                #pragma unroll
                for (int ni = 0; ni < 8; ni++) {
                    asm volatile(
                        "mma.sync.aligned.m16n8k8.row.col.f32.tf32.tf32.f32 "
                        "{%0,%1,%2,%3}, {%4,%5,%6,%7}, {%8,%9}, {%0,%1,%2,%3};\n"
                        : "+f"(acc[mi][ni][0]), "+f"(acc[mi][ni][1]),
                          "+f"(acc[mi][ni][2]), "+f"(acc[mi][ni][3])
                        : "r"(a[mi][0]), "r"(a[mi][1]), "r"(a[mi][2]), "r"(a[mi][3]),
                          "r"(b[ni][0]), "r"(b[ni][1]));
                }
        }
        __syncthreads();
        buf ^= 1;
    }

    const int g = lane >> 2, l = lane & 3;

    if (!FUSE_PROJ) {
        // Store gelu(acc + bias) to C [64 x 256], unguarded (N exact, M padded ok)
        #pragma unroll
        for (int mi = 0; mi < 2; mi++)
            #pragma unroll
            for (int ni = 0; ni < 8; ni++) {
                const int m = m0 + warpM * 32 + mi * 16 + g;
                const int n = warpN * 64 + ni * 8 + 2 * l;
                float* c = acc[mi][ni];
                C[(size_t)m * 256 + n]           = gelu_exact(c[0] + bias[n]);
                C[(size_t)m * 256 + n + 1]       = gelu_exact(c[1] + bias[n + 1]);
                C[(size_t)(m + 8) * 256 + n]     = gelu_exact(c[2] + bias[n]);
                C[(size_t)(m + 8) * 256 + n + 1] = gelu_exact(c[3] + bias[n + 1]);
            }
        return;
    }

    // ---- fused projection: out[64 x 47] = gelu(h1) @ Wo^T + bo ----
    constexpr int HP = 260;                     // h1 tile pitch (words)
    uint32_t* h1t = Ws;                         // 64*260 = 16640 <= 2*WW
    uint32_t* WoS = As;                         // 48*36 = 1728 <= 2*AW

    __syncthreads();                            // main-loop smem dead
    #pragma unroll
    for (int mi = 0; mi < 2; mi++)
        #pragma unroll
        for (int ni = 0; ni < 8; ni++) {
            const int ml = warpM * 32 + mi * 16 + g;
            const int n  = warpN * 64 + ni * 8 + 2 * l;
            float* c = acc[mi][ni];
            h1t[ml * HP + n]           = f2tf32(gelu_exact(c[0] + bias[n]));
            h1t[ml * HP + n + 1]       = f2tf32(gelu_exact(c[1] + bias[n + 1]));
            h1t[(ml + 8) * HP + n]     = f2tf32(gelu_exact(c[2] + bias[n]));
            h1t[(ml + 8) * HP + n + 1] = f2tf32(gelu_exact(c[3] + bias[n + 1]));
        }
    __syncthreads();

    const int warpM2 = warp & 3;               // 4 x 16 rows
    const int warpN2 = warp >> 2;              // 2 x 24 cols
    const int aRow2 = warpM2 * 16 + (quad & 1) * 8 + qr;
    const uint32_t h1b = (uint32_t)__cvta_generic_to_shared(h1t);
    const uint32_t wob = (uint32_t)__cvta_generic_to_shared(WoS);

    float acc2[3][4] = {};
    for (int kt = 0; kt < 8; kt++) {
        for (int i = tid; i < 48 * 32; i += 256) {
            const int r = i >> 5, cc = i & 31;
            WoS[r * SA + cc] = (r < DOUTc) ? f2tf32(Wo[(size_t)r * 256 + kt * 32 + cc]) : 0u;
        }
        __syncthreads();
        #pragma unroll
        for (int ks = 0; ks < 4; ks++) {
            uint32_t a[4], b[3][2];
            uint32_t ad = h1b + (uint32_t)(aRow2 * HP + kt * 32 + ks * 8 + aColB) * 4u;
            asm volatile("ldmatrix.sync.aligned.m8n8.x4.shared.b16 {%0,%1,%2,%3}, [%4];\n"
                         : "=r"(a[0]), "=r"(a[1]), "=r"(a[2]), "=r"(a[3])
                         : "r"(ad));
            #pragma unroll
            for (int ni = 0; ni < 3; ni++) {
                uint32_t bd = wob + (uint32_t)(((warpN2 * 24 + ni * 8 + br) * SA) + ks * 8 + bColB) * 4u;
                asm volatile("ldmatrix.sync.aligned.m8n8.x2.shared.b16 {%0,%1}, [%2];\n"
                             : "=r"(b[ni][0]), "=r"(b[ni][1])
                             : "r"(bd));
            }
            #pragma unroll
            for (int ni = 0; ni < 3; ni++) {
                asm volatile(
                    "mma.sync.aligned.m16n8k8.row.col.f32.tf32.tf32.f32 "
                    "{%0,%1,%2,%3}, {%4,%5,%6,%7}, {%8,%9}, {%0,%1,%2,%3};\n"
                    : "+f"(acc2[ni][0]), "+f"(acc2[ni][1]),
                      "+f"(acc2[ni][2]), "+f"(acc2[ni][3])
                    : "r"(a[0]), "r"(a[1]), "r"(a[2]), "r"(a[3]),
                      "r"(b[ni][0]), "r"(b[ni][1]));
            }
        }
        __syncthreads();
    }

    #pragma unroll
    for (int ni = 0; ni < 3; ni++) {
        const int m = m0 + warpM2 * 16 + g;
        const int n = warpN2 * 24 + ni * 8 + 2 * l;
        if (n < DOUTc) {
            C[(size_t)m * DOUTc + n]       = acc2[ni][0] + bo[n];
            C[(size_t)(m + 8) * DOUTc + n] = acc2[ni][2] + bo[n];
        }
        if (n + 1 < DOUTc) {
            C[(size_t)m * DOUTc + n + 1]       = acc2[ni][1] + bo[n + 1];
            C[(size_t)(m + 8) * DOUTc + n + 1] = acc2[ni][3] + bo[n + 1];
        }
    }
}

// ---------------------------------------------------------------------------
// Launch
// ---------------------------------------------------------------------------
extern "C" void kernel_launch(void* const* d_in, const int* in_sizes, int n_in,
                              void* d_out, int out_size)
{
    const float* x    = (const float*)d_in[0];
    const int*   idx0 = (const int*)  d_in[1];
    const int*   idx1 = (const int*)  d_in[3];
    const float* Wl0  = (const float*)d_in[5];
    const float* bl0  = (const float*)d_in[6];
    const float* Wr0  = (const float*)d_in[7];
    const float* Wl1  = (const float*)d_in[8];
    const float* bl1  = (const float*)d_in[9];
    const float* Wr1  = (const float*)d_in[10];
    const float* Wo   = (const float*)d_in[11];
    const float* bo   = (const float*)d_in[12];
    float* out = (float*)d_out;

    float *agg0, *h0, *agg1;
    int *mask, *list, *remap, *cnt;
    cudaGetSymbolAddress((void**)&agg0,  g_agg0);
    cudaGetSymbolAddress((void**)&h0,    g_h0);
    cudaGetSymbolAddress((void**)&agg1,  g_agg1);
    cudaGetSymbolAddress((void**)&mask,  g_mask);
    cudaGetSymbolAddress((void**)&list,  g_list);
    cudaGetSymbolAddress((void**)&remap, g_remap);
    cudaGetSymbolAddress((void**)&cnt,   g_cnt);

    const int SMEM_G  = (2 * 64 * 36 + 2 * 256 * 36) * 4;   // 92160 B
    const int SMEM_A0 = 8 * DEG0c * DINc * 4;               // 65536 B
    const int SMEM_A1 = 4 * DEG1c * DHc * 4;                // 40960 B
    cudaFuncSetAttribute(gemm_n256<false>, cudaFuncAttributeMaxDynamicSharedMemorySize, SMEM_G);
    cudaFuncSetAttribute(gemm_n256<true>,  cudaFuncAttributeMaxDynamicSharedMemorySize, SMEM_G);
    cudaFuncSetAttribute(agg_cp_kernel<DINc, DEG0c, 8, true,  false>,
                         cudaFuncAttributeMaxDynamicSharedMemorySize, SMEM_A0);
    cudaFuncSetAttribute(agg_cp_kernel<DHc,  DEG1c, 4, false, true>,
                         cudaFuncAttributeMaxDynamicSharedMemorySize, SMEM_A1);

    // Dedup: mark nodes needed by layer 1, build compact list + remap
    init_kernel<<<N1c / 256, 256>>>(mask, list, cnt);
    mark_kernel<<<(E1c + 255) / 256, 256>>>(idx1, mask);
    compact_kernel<<<N1c / 256, 256>>>(mask, list, remap, cnt);

    // Layer 0 (compact rows only): mean over 16 neighbors (D=128)
    agg_cp_kernel<DINc, DEG0c, 8, true, false>
        <<<N1c / 8, 256, SMEM_A0>>>(x, idx0, agg0, list, nullptr, cnt);

    // Layer 0 GEMM (compact rows): h0c = gelu([agg0c | x[list]] @ [Wl0|Wr0]^T + bl0)
    gemm_n256<false><<<N1c / 64, 256, SMEM_G>>>(
        agg0, x, DINc, DINc, Wl0, Wr0, bl0, h0, list, cnt, nullptr, nullptr);

    // Layer 1: mean over 10 neighbors (D=256), srcs remapped into compact h0
    agg_cp_kernel<DHc, DEG1c, 4, false, true>
        <<<N2c / 4, 256, SMEM_A1>>>(h0, idx1, agg1, nullptr, remap, nullptr);

    // Layer 1 GEMM + fused projection:
    //   out = (gelu([agg1 | h0c[remap]] @ [Wl1|Wr1]^T + bl1)) @ Wo^T + bo
    gemm_n256<true><<<N2c / 64, 256, SMEM_G>>>(
        agg1, h0, DHc, DHc, Wl1, Wr1, bl1, out, remap, nullptr, Wo, bo);
}